// round 8
// baseline (speedup 1.0000x reference)
#include <cuda_runtime.h>
#include <cuda_bf16.h>

constexpr int B  = 2;
constexpr int CF = 64;
constexpr int H  = 64;
constexpr int W  = 2048;
constexpr int CC = 3;
constexpr int C0 = 16;
constexpr int C1 = 64;

constexpr int VEC = 2;            // pixels per thread (float2)
constexpr int TPB = 256;          // threads per block
constexpr int CF_PER_BLOCK = 16;  // feature channels per block
constexpr int CF_SPLITS = CF / CF_PER_BLOCK;  // 4

__device__ __forceinline__ float2 f2zero() { return make_float2(0.f, 0.f); }
__device__ __forceinline__ float2 mul2s(float2 v, float s) {
    return make_float2(v.x * s, v.y * s);
}
__device__ __forceinline__ float2 fma2(float2 a, float2 b, float2 c) {
    return make_float2(fmaf(a.x, b.x, c.x), fmaf(a.y, b.y, c.y));
}
__device__ __forceinline__ float2 mul2(float2 a, float2 b) {
    return make_float2(a.x * b.x, a.y * b.y);
}

__global__ __launch_bounds__(TPB) void meta_fused_v7(
    const float* __restrict__ features,   // [B, CF, H, W]
    const float* __restrict__ coord,      // [B, CC, H, W]
    const float* __restrict__ w0,         // [C0, CC]
    const float* __restrict__ w1,         // [C1, C0]
    float* __restrict__ out)              // [B, CF*9, H, W]
{
    const int t       = threadIdx.x;
    const int lane    = t & 31;
    const int zb      = blockIdx.z;
    const int b       = zb / CF_SPLITS;
    const int cf_base = (zb % CF_SPLITS) * CF_PER_BLOCK;

    // Fold w1 @ w0 for this block's 16 output channels.
    __shared__ float sW[CF_PER_BLOCK * CC];
    if (t < CF_PER_BLOCK * CC) {
        const int o = cf_base + t / CC, c = t % CC;
        float s = 0.f;
        #pragma unroll
        for (int k = 0; k < C0; k++)
            s = fmaf(w1[o * C0 + k], w0[k * CC + c], s);
        sW[t] = s;
    }
    __syncthreads();

    const int g   = blockIdx.x * TPB + t;
    const int wp  = g * VEC;
    const int h   = blockIdx.y;
    const size_t chan = (size_t)H * W;
    const size_t hw   = (size_t)h * W + wp;

    const float* cbase = coord    + (size_t)b * CC * chan + hw;
    const float* fb    = features + ((size_t)b * CF + cf_base) * chan + hw;
    float*       ob    = out      + ((size_t)b * CF + cf_base) * 9 * chan + hw;

    const bool wl = (wp > 0);
    const bool wr = (wp + VEC < W);

    // Per-pixel persistent state: mask m_c (0/1) and negated center -ctr_c.
    float2 m[CC], nctr[CC];
    #pragma unroll
    for (int c = 0; c < CC; c++) {
        const float2 cc = *(const float2*)(cbase + c * chan);
        m[c]    = make_float2(cc.x == -1.f ? 0.f : 1.f,
                              cc.y == -1.f ? 0.f : 1.f);
        nctr[c] = make_float2(-cc.x, -cc.y);
    }

    #pragma unroll
    for (int di = 0; di < 3; di++) {
        const int hh = h + di - 1;
        const bool rv = (hh >= 0) && (hh < H);
        const long roff = (long)(di - 1) * W;

        // Coord row vectors for this di: aligned float2 + warp-shuffled edges.
        float2 c2[CC];
        float  cl[CC], cr[CC];
        #pragma unroll
        for (int c = 0; c < CC; c++) {
            const float* p = cbase + c * chan + roff;
            c2[c] = rv ? *(const float2*)p : f2zero();
            float l = __shfl_up_sync(0xffffffffu, c2[c].y, 1);
            float r = __shfl_down_sync(0xffffffffu, c2[c].x, 1);
            if (lane == 0)  l = (rv && wl) ? __ldg(p - 1)   : 0.f;
            if (lane == 31) r = (rv && wr) ? __ldg(p + VEC) : 0.f;
            cl[c] = l; cr[c] = r;
        }

        #pragma unroll 2
        for (int cf = 0; cf < CF_PER_BLOCK; cf++) {
            const float a0 = sW[cf * 3 + 0];
            const float a1 = sW[cf * 3 + 1];
            const float a2 = sW[cf * 3 + 2];
            const float2 b0 = mul2s(m[0], a0);
            const float2 b1 = mul2s(m[1], a1);
            const float2 b2 = mul2s(m[2], a2);
            const float2 nb = fma2(b0, nctr[0], fma2(b1, nctr[1], mul2(b2, nctr[2])));

            // Feature row: one aligned LD.64 + shuffled edges.
            const float* fp = fb + (size_t)cf * chan + roff;
            const float2 f2 = rv ? *(const float2*)fp : f2zero();
            float fl = __shfl_up_sync(0xffffffffu, f2.y, 1);
            float fr = __shfl_down_sync(0xffffffffu, f2.x, 1);
            if (lane == 0)  fl = (rv && wl) ? __ldg(fp - 1)   : 0.f;
            if (lane == 31) fr = (rv && wr) ? __ldg(fp + VEC) : 0.f;

            float* oc = ob + (size_t)(cf * 9 + di * 3) * chan;

            #pragma unroll
            for (int dj = 0; dj < 3; dj++) {
                float2 s0, s1, s2, Fv;
                if (dj == 0) {
                    s0 = make_float2(cl[0], c2[0].x);
                    s1 = make_float2(cl[1], c2[1].x);
                    s2 = make_float2(cl[2], c2[2].x);
                    Fv = make_float2(fl,    f2.x);
                } else if (dj == 1) {
                    s0 = c2[0]; s1 = c2[1]; s2 = c2[2]; Fv = f2;
                } else {
                    s0 = make_float2(c2[0].y, cr[0]);
                    s1 = make_float2(c2[1].y, cr[1]);
                    s2 = make_float2(c2[2].y, cr[2]);
                    Fv = make_float2(f2.y,    fr);
                }
                const float2 wt = fma2(b0, s0, fma2(b1, s1, fma2(b2, s2, nb)));
                float2 o2;
                o2.x = Fv.x * fmaxf(wt.x, 0.f);
                o2.y = Fv.y * fmaxf(wt.y, 0.f);
                __stcs((float2*)(oc + (size_t)dj * chan), o2);
            }
        }
    }
}

extern "C" void kernel_launch(void* const* d_in, const int* in_sizes, int n_in,
                              void* d_out, int out_size) {
    const float* features = (const float*)d_in[0];
    const float* coord    = (const float*)d_in[1];
    const float* w0       = (const float*)d_in[2];
    const float* w1       = (const float*)d_in[3];
    float* out = (float*)d_out;

    dim3 grid(W / (VEC * TPB), H, B * CF_SPLITS);   // (4, 64, 8) = 2048 blocks
    meta_fused_v7<<<grid, TPB>>>(features, coord, w0, w1, out);
}

// round 9
// speedup vs baseline: 1.2008x; 1.2008x over previous
#include <cuda_runtime.h>
#include <cuda_bf16.h>

constexpr int B  = 2;
constexpr int CF = 64;
constexpr int H  = 64;
constexpr int W  = 2048;
constexpr int CC = 3;
constexpr int C0 = 16;
constexpr int C1 = 64;

constexpr int VEC = 4;            // pixels per thread (float4)
constexpr int TPB = 256;          // threads per block
constexpr int CF_PER_BLOCK = 8;   // feature channels per block
constexpr int CF_SPLITS = CF / CF_PER_BLOCK;  // 8

__device__ __forceinline__ float4 f4zero() { return make_float4(0.f, 0.f, 0.f, 0.f); }
__device__ __forceinline__ float4 mul4s(float4 v, float s) {
    return make_float4(v.x * s, v.y * s, v.z * s, v.w * s);
}
__device__ __forceinline__ float4 fma4(float4 a, float4 b, float4 c) {
    return make_float4(fmaf(a.x, b.x, c.x), fmaf(a.y, b.y, c.y),
                       fmaf(a.z, b.z, c.z), fmaf(a.w, b.w, c.w));
}
__device__ __forceinline__ float4 mul4(float4 a, float4 b) {
    return make_float4(a.x * b.x, a.y * b.y, a.z * b.z, a.w * b.w);
}

__global__ __launch_bounds__(TPB) void meta_fused_v8(
    const float* __restrict__ features,   // [B, CF, H, W]
    const float* __restrict__ coord,      // [B, CC, H, W]
    const float* __restrict__ w0,         // [C0, CC]
    const float* __restrict__ w1,         // [C1, C0]
    float* __restrict__ out)              // [B, CF*9, H, W]
{
    const int t       = threadIdx.x;
    const int lane    = t & 31;
    const int zb      = blockIdx.z;
    const int b       = zb / CF_SPLITS;
    const int cf_base = (zb % CF_SPLITS) * CF_PER_BLOCK;

    // Fold w1 @ w0 for this block's 8 output channels.
    __shared__ float sW[CF_PER_BLOCK * CC];
    if (t < CF_PER_BLOCK * CC) {
        const int o = cf_base + t / CC, c = t % CC;
        float s = 0.f;
        #pragma unroll
        for (int k = 0; k < C0; k++)
            s = fmaf(w1[o * C0 + k], w0[k * CC + c], s);
        sW[t] = s;
    }
    __syncthreads();

    const int g   = blockIdx.x * TPB + t;
    const int wp  = g * VEC;
    const int h   = blockIdx.y;
    const size_t chan = (size_t)H * W;
    const size_t hw   = (size_t)h * W + wp;

    const float* cbase = coord    + (size_t)b * CC * chan + hw;
    const float* fb    = features + ((size_t)b * CF + cf_base) * chan + hw;
    float*       ob    = out      + ((size_t)b * CF + cf_base) * 9 * chan + hw;

    const bool wl = (wp > 0);
    const bool wr = (wp + VEC < W);

    // Per-pixel persistent state: mask m_c (0/1) and negated center -ctr_c.
    // wt[n] = sum_c (m_c*a_c)*s_c[n] - sum_c (m_c*a_c)*ctr_c
    float4 m[CC], nctr[CC];
    #pragma unroll
    for (int c = 0; c < CC; c++) {
        const float4 cc = *(const float4*)(cbase + c * chan);
        m[c] = make_float4(cc.x == -1.f ? 0.f : 1.f,
                           cc.y == -1.f ? 0.f : 1.f,
                           cc.z == -1.f ? 0.f : 1.f,
                           cc.w == -1.f ? 0.f : 1.f);
        nctr[c] = make_float4(-cc.x, -cc.y, -cc.z, -cc.w);
    }

    #pragma unroll
    for (int di = 0; di < 3; di++) {
        const int hh = h + di - 1;
        const bool rv = (hh >= 0) && (hh < H);
        const long roff = (long)(di - 1) * W;

        // Coord row vectors for this di: aligned vec4 + warp-shuffled edges.
        float4 c4[CC];
        float  cl[CC], cr[CC];
        #pragma unroll
        for (int c = 0; c < CC; c++) {
            const float* p = cbase + c * chan + roff;
            c4[c] = rv ? *(const float4*)p : f4zero();
            float l = __shfl_up_sync(0xffffffffu, c4[c].w, 1);
            float r = __shfl_down_sync(0xffffffffu, c4[c].x, 1);
            if (lane == 0)  l = (rv && wl) ? __ldg(p - 1)   : 0.f;
            if (lane == 31) r = (rv && wr) ? __ldg(p + VEC) : 0.f;
            cl[c] = l; cr[c] = r;
        }

        #pragma unroll 2
        for (int cf = 0; cf < CF_PER_BLOCK; cf++) {
            const float a0 = sW[cf * 3 + 0];
            const float a1 = sW[cf * 3 + 1];
            const float a2 = sW[cf * 3 + 2];
            const float4 b0 = mul4s(m[0], a0);
            const float4 b1 = mul4s(m[1], a1);
            const float4 b2 = mul4s(m[2], a2);
            const float4 nb = fma4(b0, nctr[0], fma4(b1, nctr[1], mul4(b2, nctr[2])));

            // Feature row: one aligned LD.128 + shuffled edges.
            const float* fp = fb + (size_t)cf * chan + roff;
            const float4 f4 = rv ? *(const float4*)fp : f4zero();
            float fl = __shfl_up_sync(0xffffffffu, f4.w, 1);
            float fr = __shfl_down_sync(0xffffffffu, f4.x, 1);
            if (lane == 0)  fl = (rv && wl) ? __ldg(fp - 1)   : 0.f;
            if (lane == 31) fr = (rv && wr) ? __ldg(fp + VEC) : 0.f;

            float* oc = ob + (size_t)(cf * 9 + di * 3) * chan;

            #pragma unroll
            for (int dj = 0; dj < 3; dj++) {
                float4 s0, s1, s2, Fv;
                if (dj == 0) {
                    s0 = make_float4(cl[0], c4[0].x, c4[0].y, c4[0].z);
                    s1 = make_float4(cl[1], c4[1].x, c4[1].y, c4[1].z);
                    s2 = make_float4(cl[2], c4[2].x, c4[2].y, c4[2].z);
                    Fv = make_float4(fl,    f4.x,    f4.y,    f4.z);
                } else if (dj == 1) {
                    s0 = c4[0]; s1 = c4[1]; s2 = c4[2]; Fv = f4;
                } else {
                    s0 = make_float4(c4[0].y, c4[0].z, c4[0].w, cr[0]);
                    s1 = make_float4(c4[1].y, c4[1].z, c4[1].w, cr[1]);
                    s2 = make_float4(c4[2].y, c4[2].z, c4[2].w, cr[2]);
                    Fv = make_float4(f4.y,    f4.z,    f4.w,    fr);
                }
                const float4 wt = fma4(b0, s0, fma4(b1, s1, fma4(b2, s2, nb)));
                float4 o4;
                o4.x = Fv.x * fmaxf(wt.x, 0.f);
                o4.y = Fv.y * fmaxf(wt.y, 0.f);
                o4.z = Fv.z * fmaxf(wt.z, 0.f);
                o4.w = Fv.w * fmaxf(wt.w, 0.f);
                __stcs((float4*)(oc + (size_t)dj * chan), o4);
            }
        }
    }
}

extern "C" void kernel_launch(void* const* d_in, const int* in_sizes, int n_in,
                              void* d_out, int out_size) {
    const float* features = (const float*)d_in[0];
    const float* coord    = (const float*)d_in[1];
    const float* w0       = (const float*)d_in[2];
    const float* w1       = (const float*)d_in[3];
    float* out = (float*)d_out;

    dim3 grid(W / (VEC * TPB), H, B * CF_SPLITS);   // (2, 64, 16) = 2048 blocks
    meta_fused_v8<<<grid, TPB>>>(features, coord, w0, w1, out);
}